// round 3
// baseline (speedup 1.0000x reference)
#include <cuda_runtime.h>

#define Ssz   2304
#define Csz   256
#define Bbat  8
#define BSC   (Bbat*Ssz*Csz)

// ---- scratch ---------------------------------------------------------------
__device__ float g_xln[2][BSC];
__device__ float g_q[2][BSC];
__device__ float g_k[2][BSC];
__device__ float g_v[2][BSC];
__device__ float g_E[(size_t)Bbat*Ssz*Ssz];
__device__ float g_O[BSC];
__device__ float g_Wt[4][Csz*Csz];

// ---- helpers ---------------------------------------------------------------
__device__ __forceinline__ float tf32r(float x) {
    unsigned u; asm("cvt.rna.tf32.f32 %0, %1;" : "=r"(u) : "f"(x));
    return __uint_as_float(u);
}
__device__ __forceinline__ void mma_tf32(float acc[4], const unsigned a[4], const unsigned b[2]) {
    asm volatile(
        "mma.sync.aligned.m16n8k8.row.col.f32.tf32.tf32.f32 "
        "{%0,%1,%2,%3}, {%4,%5,%6,%7}, {%8,%9}, {%0,%1,%2,%3};\n"
        : "+f"(acc[0]), "+f"(acc[1]), "+f"(acc[2]), "+f"(acc[3])
        : "r"(a[0]), "r"(a[1]), "r"(a[2]), "r"(a[3]), "r"(b[0]), "r"(b[1]));
}
__device__ __forceinline__ void cp16(unsigned dst, const void* src) {
    asm volatile("cp.async.ca.shared.global [%0], [%1], 16;\n" :: "r"(dst), "l"(src));
}
__device__ __forceinline__ void cp_commit() {
    asm volatile("cp.async.commit_group;\n" ::: "memory");
}
__device__ __forceinline__ void cp_wait1() {
    asm volatile("cp.async.wait_group 1;\n" ::: "memory");
}

#define STAGE_B   36864          // bytes per pipeline stage (A 18432 + B <=18432)
#define SMEM_DYN  (3*STAGE_B)    // 108 KB

// ---- weight convert: round 4 weight matrices to tf32 -----------------------
__global__ void wconv_kernel(const float* __restrict__ wq, const float* __restrict__ wk,
                             const float* __restrict__ wv, const float* __restrict__ wo,
                             float* __restrict__ wt) {
    int i = blockIdx.x * 256 + threadIdx.x;
    wt[0*Csz*Csz + i] = tf32r(wq[i]);
    wt[1*Csz*Csz + i] = tf32r(wk[i]);
    wt[2*Csz*Csz + i] = tf32r(wv[i]);
    wt[3*Csz*Csz + i] = tf32r(wo[i]);
}

// ---- LayerNorm over C + transpose [B,C,S]->[B,S,C], tf32-rounded out -------
__global__ __launch_bounds__(256, 2) void ln_kernel(
    const float* __restrict__ xl, const float* __restrict__ xr,
    const float* __restrict__ g1, const float* __restrict__ b1,
    const float* __restrict__ g2, const float* __restrict__ b2,
    float* __restrict__ xlnL, float* __restrict__ xlnR)
{
    const int side = blockIdx.z;
    const float* x  = side ? xr : xl;
    const float* g  = side ? g2 : g1;
    const float* bb = side ? b2 : b1;
    float* xo = side ? xlnR : xlnL;

    const int b  = blockIdx.y;
    const int s0 = blockIdx.x * 32;
    const int tid = threadIdx.x;
    const int tx = tid & 31, ty = tid >> 5;

    __shared__ float xs[256][33];
    __shared__ float ps[8][32], ps2[8][32];
    __shared__ float mu[32], rs[32];

    const float* xb = x + (size_t)b * Csz * Ssz;
    #pragma unroll
    for (int cc = 0; cc < 32; cc++) {
        int c = cc * 8 + ty;
        xs[c][tx] = xb[(size_t)c * Ssz + s0 + tx];
    }
    __syncthreads();

    float sum = 0.f, sq = 0.f;
    #pragma unroll
    for (int i = 0; i < 32; i++) {
        float v = xs[ty * 32 + i][tx];
        sum += v; sq += v * v;
    }
    ps[ty][tx] = sum; ps2[ty][tx] = sq;
    __syncthreads();

    if (ty == 0) {
        float s1 = 0.f, s2 = 0.f;
        #pragma unroll
        for (int j = 0; j < 8; j++) { s1 += ps[j][tx]; s2 += ps2[j][tx]; }
        float m = s1 * (1.f / 256.f);
        float v = s2 * (1.f / 256.f) - m * m;
        mu[tx] = m;
        rs[tx] = rsqrtf(v + 1e-5f);
    }
    __syncthreads();

    const float gc = g[tid], bc = bb[tid];
    float* xob = xo + ((size_t)b * Ssz + s0) * Csz;
    #pragma unroll
    for (int si = 0; si < 32; si++)
        xob[si * Csz + tid] = tf32r((xs[tid][si] - mu[si]) * rs[si] * gc + bc);
}

// ---- TF32 GEMM w/ cp.async 3-stage pipeline --------------------------------
// C[M,128-tile] = A[M,K] @ B[K,N];  A rows k-contig, B rows n-contig (NN).
// MODE 0: store tf32-rounded. MODE 1: out = resid + acc, transposed to [B,C,S].
template<int MODE>
__global__ __launch_bounds__(256, 2) void gemm_cp(
    const float* __restrict__ A, int lda, long sA,
    const float* __restrict__ Bw, int ldb, long sB,
    float* __restrict__ C, long sC, int K,
    const float* __restrict__ resid)
{
    extern __shared__ char smem[];
    const int tid = threadIdx.x, lane = tid & 31, warp = tid >> 5;
    const int wm = (warp >> 2) * 64, wn = (warp & 3) * 32;
    const int grp = lane >> 2, tg = lane & 3;
    const int n0 = blockIdx.x * 128, m0 = blockIdx.y * 128;
    A  += (long)blockIdx.z * sA;
    Bw += (long)blockIdx.z * sB;
    C  += (long)blockIdx.z * sC;

    const unsigned sbase = (unsigned)__cvta_generic_to_shared(smem);

    // A: 128 rows x 32 floats; thread -> row=tid>>1, half=(tid&1)*16 floats
    const int arow = tid >> 1, ahalf = (tid & 1) * 16;
    // B: 32 rows x 128 floats; thread -> row=tid>>3, 64B seg=(tid&7)*16 floats
    const int brow = tid >> 3, bseg = (tid & 7) * 16;

    auto ldA = [&](int kc, int stg) {
        const float* src = &A[(long)(m0 + arow) * lda + kc * 32 + ahalf];
        unsigned dst = sbase + stg * STAGE_B + (arow * 36 + ahalf) * 4;
        #pragma unroll
        for (int j = 0; j < 4; j++) cp16(dst + j * 16, src + j * 4);
    };
    auto ldB = [&](int kc, int stg) {
        const float* src = &Bw[(long)(kc * 32 + brow) * ldb + n0 + bseg];
        unsigned dst = sbase + stg * STAGE_B + 18432 + (brow * 136 + bseg) * 4;
        #pragma unroll
        for (int j = 0; j < 4; j++) cp16(dst + j * 16, src + j * 4);
    };

    float acc[4][4][4];
    #pragma unroll
    for (int i = 0; i < 4; i++)
        #pragma unroll
        for (int j = 0; j < 4; j++)
            #pragma unroll
            for (int r = 0; r < 4; r++) acc[i][j][r] = 0.f;

    const int nk = K >> 5;
    ldA(0, 0); ldB(0, 0); cp_commit();
    ldA(1, 1); ldB(1, 1); cp_commit();

    for (int kc = 0; kc < nk; kc++) {
        cp_wait1();
        __syncthreads();
        const int stg = kc % 3;
        if (kc + 2 < nk) { ldA(kc + 2, (kc + 2) % 3); ldB(kc + 2, (kc + 2) % 3); }
        cp_commit();

        const float* As = (const float*)(smem + stg * STAGE_B);
        const float* Bs = (const float*)(smem + stg * STAGE_B + 18432);
        #pragma unroll
        for (int ks = 0; ks < 4; ks++) {
            const int k0 = ks * 8;
            unsigned af[4][4], bf[4][2];
            #pragma unroll
            for (int mi = 0; mi < 4; mi++) {
                int rm = wm + mi * 16;
                af[mi][0] = __float_as_uint(As[(rm + grp    ) * 36 + k0 + tg    ]);
                af[mi][1] = __float_as_uint(As[(rm + grp + 8) * 36 + k0 + tg    ]);
                af[mi][2] = __float_as_uint(As[(rm + grp    ) * 36 + k0 + tg + 4]);
                af[mi][3] = __float_as_uint(As[(rm + grp + 8) * 36 + k0 + tg + 4]);
            }
            #pragma unroll
            for (int ni = 0; ni < 4; ni++) {
                int cn = wn + ni * 8 + grp;
                bf[ni][0] = __float_as_uint(Bs[(k0 + tg    ) * 136 + cn]);
                bf[ni][1] = __float_as_uint(Bs[(k0 + tg + 4) * 136 + cn]);
            }
            #pragma unroll
            for (int mi = 0; mi < 4; mi++)
                #pragma unroll
                for (int ni = 0; ni < 4; ni++)
                    mma_tf32(acc[mi][ni], af[mi], bf[ni]);
        }
    }

    #pragma unroll
    for (int mi = 0; mi < 4; mi++) {
        #pragma unroll
        for (int ni = 0; ni < 4; ni++) {
            if (MODE == 0) {
                int r0 = m0 + wm + mi * 16 + grp;
                int c0 = n0 + wn + ni * 8 + tg * 2;
                *reinterpret_cast<float2*>(&C[(long)r0 * 256 + c0]) =
                    make_float2(tf32r(acc[mi][ni][0]), tf32r(acc[mi][ni][1]));
                *reinterpret_cast<float2*>(&C[(long)(r0 + 8) * 256 + c0]) =
                    make_float2(tf32r(acc[mi][ni][2]), tf32r(acc[mi][ni][3]));
            } else {
                int m  = m0 + wm + mi * 16 + grp;
                int bb = m / Ssz;
                int ss = m - bb * Ssz;
                int c  = n0 + wn + ni * 8 + tg * 2;
                long o0 = ((long)bb * 256 + c) * Ssz + ss;
                C[o0          ] = resid[o0          ] + acc[mi][ni][0];
                C[o0 + Ssz    ] = resid[o0 + Ssz    ] + acc[mi][ni][1];
                C[o0 + 8      ] = resid[o0 + 8      ] + acc[mi][ni][2];
                C[o0 + Ssz + 8] = resid[o0 + Ssz + 8] + acc[mi][ni][3];
            }
        }
    }
}

// ---- scores: E[b,s,t] = exp(Q[b,s,:].K[b,t,:]/16) (raw fp32) ---------------
// grid (S/128 t, S/128 s); loops 8 batches in-CTA; NT layout both operands.
__global__ __launch_bounds__(256, 2) void attn_scores(
    const float* __restrict__ Q, const float* __restrict__ Ko,
    float* __restrict__ E)
{
    extern __shared__ char smem[];
    const int tid = threadIdx.x, lane = tid & 31, warp = tid >> 5;
    const int wm = (warp >> 2) * 64, wn = (warp & 3) * 32;
    const int grp = lane >> 2, tg = lane & 3;
    const int t0 = blockIdx.x * 128, s0 = blockIdx.y * 128;

    const unsigned sbase = (unsigned)__cvta_generic_to_shared(smem);
    const int arow = tid >> 1, ahalf = (tid & 1) * 16;

    auto ld = [&](int it, int stg) {
        int b = it >> 3, kc = it & 7;
        const float* srcA = &Q [((long)b * Ssz + s0 + arow) * 256 + kc * 32 + ahalf];
        const float* srcB = &Ko[((long)b * Ssz + t0 + arow) * 256 + kc * 32 + ahalf];
        unsigned da = sbase + stg * STAGE_B + (arow * 36 + ahalf) * 4;
        unsigned db = da + 18432;
        #pragma unroll
        for (int j = 0; j < 4; j++) {
            cp16(da + j * 16, srcA + j * 4);
            cp16(db + j * 16, srcB + j * 4);
        }
    };

    float acc[4][4][4];
    ld(0, 0); cp_commit();
    ld(1, 1); cp_commit();

    for (int it = 0; it < 64; it++) {
        cp_wait1();
        __syncthreads();
        const int stg = it % 3;
        if (it + 2 < 64) ld(it + 2, (it + 2) % 3);
        cp_commit();

        const int kc = it & 7;
        if (kc == 0) {
            #pragma unroll
            for (int i = 0; i < 4; i++)
                #pragma unroll
                for (int j = 0; j < 4; j++)
                    #pragma unroll
                    for (int r = 0; r < 4; r++) acc[i][j][r] = 0.f;
        }

        const float* As = (const float*)(smem + stg * STAGE_B);
        const float* Bs = As + 18432 / 4;
        #pragma unroll
        for (int ks = 0; ks < 4; ks++) {
            const int k0 = ks * 8;
            unsigned af[4][4], bf[4][2];
            #pragma unroll
            for (int mi = 0; mi < 4; mi++) {
                int rm = wm + mi * 16;
                af[mi][0] = __float_as_uint(As[(rm + grp    ) * 36 + k0 + tg    ]);
                af[mi][1] = __float_as_uint(As[(rm + grp + 8) * 36 + k0 + tg    ]);
                af[mi][2] = __float_as_uint(As[(rm + grp    ) * 36 + k0 + tg + 4]);
                af[mi][3] = __float_as_uint(As[(rm + grp + 8) * 36 + k0 + tg + 4]);
            }
            #pragma unroll
            for (int ni = 0; ni < 4; ni++) {
                int cn = wn + ni * 8 + grp;
                bf[ni][0] = __float_as_uint(Bs[cn * 36 + k0 + tg    ]);
                bf[ni][1] = __float_as_uint(Bs[cn * 36 + k0 + tg + 4]);
            }
            #pragma unroll
            for (int mi = 0; mi < 4; mi++)
                #pragma unroll
                for (int ni = 0; ni < 4; ni++)
                    mma_tf32(acc[mi][ni], af[mi], bf[ni]);
        }

        if (kc == 7) {
            const int b = it >> 3;
            float* Eb = E + (long)b * Ssz * Ssz;
            #pragma unroll
            for (int mi = 0; mi < 4; mi++) {
                #pragma unroll
                for (int ni = 0; ni < 4; ni++) {
                    int r0 = s0 + wm + mi * 16 + grp;
                    int c0 = t0 + wn + ni * 8 + tg * 2;
                    float e0 = __expf(acc[mi][ni][0] * 0.0625f);
                    float e1 = __expf(acc[mi][ni][1] * 0.0625f);
                    float e2 = __expf(acc[mi][ni][2] * 0.0625f);
                    float e3 = __expf(acc[mi][ni][3] * 0.0625f);
                    *reinterpret_cast<float2*>(&Eb[(long)r0 * Ssz + c0]) = make_float2(e0, e1);
                    *reinterpret_cast<float2*>(&Eb[(long)(r0 + 8) * Ssz + c0]) = make_float2(e2, e3);
                }
            }
        }
    }
}

// ---- normalize: E[b,s,t] *= 1/sum_b E[b,s,t], rounded to tf32 (in place) ---
__global__ __launch_bounds__(256, 4) void normalize_kernel(float* __restrict__ E)
{
    const long SS = (long)Ssz * Ssz;
    long i = ((long)blockIdx.x * 256 + threadIdx.x) * 4;
    float4 e[Bbat];
    float4 s = make_float4(0.f, 0.f, 0.f, 0.f);
    #pragma unroll
    for (int b = 0; b < Bbat; b++) {
        e[b] = *reinterpret_cast<const float4*>(&E[b * SS + i]);
        s.x += e[b].x; s.y += e[b].y; s.z += e[b].z; s.w += e[b].w;
    }
    float4 inv = make_float4(1.f / s.x, 1.f / s.y, 1.f / s.z, 1.f / s.w);
    #pragma unroll
    for (int b = 0; b < Bbat; b++) {
        *reinterpret_cast<float4*>(&E[b * SS + i]) =
            make_float4(tf32r(e[b].x * inv.x), tf32r(e[b].y * inv.y),
                        tf32r(e[b].z * inv.z), tf32r(e[b].w * inv.w));
    }
}

// ---- launch ----------------------------------------------------------------
extern "C" void kernel_launch(void* const* d_in, const int* in_sizes, int n_in,
                              void* d_out, int out_size) {
    const float* x_l = (const float*)d_in[0];
    const float* x_r = (const float*)d_in[1];
    const float* Wq  = (const float*)d_in[2];
    const float* Wk  = (const float*)d_in[3];
    const float* Wv  = (const float*)d_in[4];
    const float* Wo  = (const float*)d_in[5];
    const float* g1  = (const float*)d_in[6];
    const float* b1  = (const float*)d_in[7];
    const float* g2  = (const float*)d_in[8];
    const float* b2  = (const float*)d_in[9];
    float* out = (float*)d_out;

    float *xln, *q, *k, *v, *E, *O, *Wt;
    cudaGetSymbolAddress((void**)&xln, g_xln);
    cudaGetSymbolAddress((void**)&q,   g_q);
    cudaGetSymbolAddress((void**)&k,   g_k);
    cudaGetSymbolAddress((void**)&v,   g_v);
    cudaGetSymbolAddress((void**)&E,   g_E);
    cudaGetSymbolAddress((void**)&O,   g_O);
    cudaGetSymbolAddress((void**)&Wt,  g_Wt);

    cudaFuncSetAttribute(gemm_cp<0>, cudaFuncAttributeMaxDynamicSharedMemorySize, SMEM_DYN);
    cudaFuncSetAttribute(gemm_cp<1>, cudaFuncAttributeMaxDynamicSharedMemorySize, SMEM_DYN);
    cudaFuncSetAttribute(attn_scores, cudaFuncAttributeMaxDynamicSharedMemorySize, SMEM_DYN);

    wconv_kernel<<<256, 256>>>(Wq, Wk, Wv, Wo, Wt);
    ln_kernel<<<dim3(Ssz / 32, Bbat, 2), 256>>>(x_l, x_r, g1, b1, g2, b2,
                                                xln, xln + BSC);

    const dim3 gProj(2, (Bbat * Ssz) / 128, 1);
    for (int s = 0; s < 2; s++) {
        gemm_cp<0><<<gProj, 256, SMEM_DYN>>>(xln + s * BSC, 256, 0,
                                             Wt + 0 * Csz * Csz, 256, 0,
                                             q + s * BSC, 0, 256, nullptr);
        gemm_cp<0><<<gProj, 256, SMEM_DYN>>>(xln + s * BSC, 256, 0,
                                             Wt + 1 * Csz * Csz, 256, 0,
                                             k + s * BSC, 0, 256, nullptr);
        gemm_cp<0><<<gProj, 256, SMEM_DYN>>>(xln + s * BSC, 256, 0,
                                             Wt + 2 * Csz * Csz, 256, 0,
                                             v + s * BSC, 0, 256, nullptr);
    }

    const long SS = (long)Ssz * Ssz;
    for (int s = 0; s < 2; s++) {
        attn_scores<<<dim3(Ssz / 128, Ssz / 128), 256, SMEM_DYN>>>(
            q + s * BSC, k + (1 - s) * BSC, E);
        normalize_kernel<<<(int)(SS / 1024), 256>>>(E);
        gemm_cp<0><<<dim3(2, Ssz / 128, Bbat), 256, SMEM_DYN>>>(
            E, Ssz, SS, v + s * BSC, 256, (long)Ssz * 256,
            O, (long)Ssz * 256, Ssz, nullptr);
        gemm_cp<1><<<gProj, 256, SMEM_DYN>>>(O, 256, 0,
                                             Wt + 3 * Csz * Csz, 256, 0,
                                             out + s * BSC, 0, 256, s ? x_r : x_l);
    }
}

// round 5
// speedup vs baseline: 1.4847x; 1.4847x over previous
#include <cuda_runtime.h>
#include <cstdint>

#define Ssz   2304
#define Csz   256
#define Bbat  8
#define BSC   (Bbat*Ssz*Csz)
#define SSl   ((long)Ssz*Ssz)

// ---- scratch ---------------------------------------------------------------
__device__ float g_xln[2][BSC];
__device__ float g_q[2][BSC];
__device__ float g_k[2][BSC];
__device__ float g_v[2][BSC];
__device__ float g_E[(size_t)Bbat*Ssz*Ssz];
__device__ float g_O[BSC];
__device__ float g_Wt[4][Csz*Csz];

// ---- helpers ---------------------------------------------------------------
__device__ __forceinline__ float tf32r(float x) {
    unsigned u; asm("cvt.rna.tf32.f32 %0, %1;" : "=r"(u) : "f"(x));
    return __uint_as_float(u);
}
__device__ __forceinline__ void mma_tf32(float acc[4], const unsigned a[4], const unsigned b[2]) {
    asm volatile(
        "mma.sync.aligned.m16n8k8.row.col.f32.tf32.tf32.f32 "
        "{%0,%1,%2,%3}, {%4,%5,%6,%7}, {%8,%9}, {%0,%1,%2,%3};\n"
        : "+f"(acc[0]), "+f"(acc[1]), "+f"(acc[2]), "+f"(acc[3])
        : "r"(a[0]), "r"(a[1]), "r"(a[2]), "r"(a[3]), "r"(b[0]), "r"(b[1]));
}

// stage layouts (floats):
//  gemm:   As 128*36 = 4608 | Bs 32*264 = 8448  -> stage 13056 fl (52224 B)
//  scores: Qs 128*36 = 4608 | Ks 256*36 = 9216  -> stage 13824 fl (55296 B)
#define G_STG   13056
#define S_STG   13824
#define SMEM_G  (2*G_STG*4)
#define SMEM_S  (2*S_STG*4)

// ---- weight convert: tf32 round (no transpose; W is [k][n] n-contig) -------
__global__ void wconv_kernel(const float* __restrict__ wq, const float* __restrict__ wk,
                             const float* __restrict__ wv, const float* __restrict__ wo,
                             float* __restrict__ wt) {
    int i = blockIdx.x * 256 + threadIdx.x;
    wt[0*Csz*Csz + i] = tf32r(wq[i]);
    wt[1*Csz*Csz + i] = tf32r(wk[i]);
    wt[2*Csz*Csz + i] = tf32r(wv[i]);
    wt[3*Csz*Csz + i] = tf32r(wo[i]);
}

// ---- LayerNorm over C + transpose [B,C,S]->[B,S,C], tf32 out ---------------
__global__ __launch_bounds__(256, 2) void ln_kernel(
    const float* __restrict__ xl, const float* __restrict__ xr,
    const float* __restrict__ g1, const float* __restrict__ b1,
    const float* __restrict__ g2, const float* __restrict__ b2,
    float* __restrict__ xlnL, float* __restrict__ xlnR)
{
    const int side = blockIdx.z;
    const float* x  = side ? xr : xl;
    const float* g  = side ? g2 : g1;
    const float* bb = side ? b2 : b1;
    float* xo = side ? xlnR : xlnL;

    const int b  = blockIdx.y;
    const int s0 = blockIdx.x * 32;
    const int tid = threadIdx.x;
    const int tx = tid & 31, ty = tid >> 5;

    __shared__ float xs[256][33];
    __shared__ float ps[8][32], ps2[8][32];
    __shared__ float mu[32], rs[32];

    const float* xb = x + (size_t)b * Csz * Ssz;
    #pragma unroll
    for (int cc = 0; cc < 32; cc++) {
        int c = cc * 8 + ty;
        xs[c][tx] = xb[(size_t)c * Ssz + s0 + tx];
    }
    __syncthreads();

    float sum = 0.f, sq = 0.f;
    #pragma unroll
    for (int i = 0; i < 32; i++) {
        float v = xs[ty * 32 + i][tx];
        sum += v; sq += v * v;
    }
    ps[ty][tx] = sum; ps2[ty][tx] = sq;
    __syncthreads();

    if (ty == 0) {
        float s1 = 0.f, s2 = 0.f;
        #pragma unroll
        for (int j = 0; j < 8; j++) { s1 += ps[j][tx]; s2 += ps2[j][tx]; }
        float m = s1 * (1.f / 256.f);
        float v = s2 * (1.f / 256.f) - m * m;
        mu[tx] = m;
        rs[tx] = rsqrtf(v + 1e-5f);
    }
    __syncthreads();

    const float gc = g[tid], bc = bb[tid];
    float* xob = xo + ((size_t)b * Ssz + s0) * Csz;
    #pragma unroll
    for (int si = 0; si < 32; si++)
        xob[si * Csz + tid] = tf32r((xs[tid][si] - mu[si]) * rs[si] * gc + bc);
}

// ---- TF32 GEMM: C[M,256] = A[M,K] @ B[K,256] -------------------------------
// CTA 128x256, 8 warps (2m x 4n), warp tile 64x64, K-chunk 32, double-buffer.
// Operands pre-rounded to tf32. MODE 0: C = tf32(acc). MODE 2: residual+transpose.
template<int MODE>
__global__ __launch_bounds__(256) void gemm_tc(
    const float* __restrict__ A, int lda, long sA,
    const float* __restrict__ Bw, int ldb, long sB,
    float* __restrict__ C, long sC, int K,
    const float* __restrict__ resid)
{
    extern __shared__ float sm[];
    const int tid = threadIdx.x, lane = tid & 31, wid = tid >> 5;
    const int grp = lane >> 2, tg = lane & 3;
    const int wm = (wid & 1) * 64, wn = (wid >> 1) * 64;
    const int m0 = blockIdx.x * 128;
    const int z = blockIdx.y;
    A  += (long)z * sA;
    Bw += (long)z * sB;
    C  += (long)z * sC;

    // loaders: A 128x32 (4 passes of 32 rows), B 32x256 (8 col-groups)
    const int lr = tid >> 3, lc = (tid & 7) * 4;
    float4 ra[4], rb[8];

    auto ldg = [&](int kc) {
        #pragma unroll
        for (int p = 0; p < 4; p++)
            ra[p] = *(const float4*)&A[(long)(m0 + lr + p * 32) * lda + kc * 32 + lc];
        #pragma unroll
        for (int j = 0; j < 8; j++)
            rb[j] = *(const float4*)&Bw[(long)(kc * 32 + lr) * ldb + lc + j * 32];
    };
    auto sts = [&](int stg) {
        float* As = sm + stg * G_STG;
        float* Bs = As + 4608;
        #pragma unroll
        for (int p = 0; p < 4; p++)
            *(float4*)&As[(lr + p * 32) * 36 + lc] = ra[p];
        #pragma unroll
        for (int j = 0; j < 8; j++)
            *(float4*)&Bs[lr * 264 + lc + j * 32] = rb[j];
    };

    float acc[4][8][4];
    #pragma unroll
    for (int i = 0; i < 4; i++)
        #pragma unroll
        for (int j = 0; j < 8; j++)
            #pragma unroll
            for (int r = 0; r < 4; r++) acc[i][j][r] = 0.f;

    const int nch = K >> 5;
    ldg(0); sts(0); __syncthreads();

    for (int ic = 0; ic < nch; ic++) {
        const int stg = ic & 1;
        if (ic + 1 < nch) ldg(ic + 1);

        const float* As = sm + stg * G_STG;
        const float* Bs = As + 4608;
        #pragma unroll
        for (int ks = 0; ks < 4; ks++) {
            const int k0 = ks * 8;
            unsigned af[4][4], bf[8][2];
            #pragma unroll
            for (int mi = 0; mi < 4; mi++) {
                int rm = wm + mi * 16;
                af[mi][0] = __float_as_uint(As[(rm + grp    ) * 36 + k0 + tg    ]);
                af[mi][1] = __float_as_uint(As[(rm + grp + 8) * 36 + k0 + tg    ]);
                af[mi][2] = __float_as_uint(As[(rm + grp    ) * 36 + k0 + tg + 4]);
                af[mi][3] = __float_as_uint(As[(rm + grp + 8) * 36 + k0 + tg + 4]);
            }
            #pragma unroll
            for (int ni = 0; ni < 8; ni++) {
                int cn = wn + ni * 8 + grp;
                bf[ni][0] = __float_as_uint(Bs[(k0 + tg    ) * 264 + cn]);
                bf[ni][1] = __float_as_uint(Bs[(k0 + tg + 4) * 264 + cn]);
            }
            #pragma unroll
            for (int mi = 0; mi < 4; mi++)
                #pragma unroll
                for (int ni = 0; ni < 8; ni++)
                    mma_tf32(acc[mi][ni], af[mi], bf[ni]);
        }
        if (ic + 1 < nch) { sts(stg ^ 1); __syncthreads(); }
    }

    #pragma unroll
    for (int mi = 0; mi < 4; mi++) {
        #pragma unroll
        for (int ni = 0; ni < 8; ni++) {
            int r0 = m0 + wm + mi * 16 + grp;
            int c0 = wn + ni * 8 + tg * 2;
            if (MODE == 0) {
                *(float2*)&C[(long)r0 * 256 + c0] =
                    make_float2(tf32r(acc[mi][ni][0]), tf32r(acc[mi][ni][1]));
                *(float2*)&C[(long)(r0 + 8) * 256 + c0] =
                    make_float2(tf32r(acc[mi][ni][2]), tf32r(acc[mi][ni][3]));
            } else {
                int bb = r0 / Ssz;
                int ss = r0 - bb * Ssz;
                long a0 = ((long)(bb * 256 + c0)) * Ssz + ss;
                C[a0          ] = resid[a0          ] + acc[mi][ni][0];
                C[a0 + Ssz    ] = resid[a0 + Ssz    ] + acc[mi][ni][1];
                C[a0 + 8      ] = resid[a0 + 8      ] + acc[mi][ni][2];
                C[a0 + Ssz + 8] = resid[a0 + Ssz + 8] + acc[mi][ni][3];
            }
        }
    }
}

// ---- scores: E[b,s,t] = exp(Q[b]·K[b]^T / 16), raw fp32 --------------------
// CTA 128s x 256t, 8 batches looped in-CTA, same warp layout as gemm_tc.
__global__ __launch_bounds__(256) void tc_scores(
    const float* __restrict__ Q, const float* __restrict__ Ko,
    float* __restrict__ E)
{
    extern __shared__ float sm[];
    const int tid = threadIdx.x, lane = tid & 31, wid = tid >> 5;
    const int grp = lane >> 2, tg = lane & 3;
    const int wm = (wid & 1) * 64, wn = (wid >> 1) * 64;
    const int s0 = blockIdx.y * 128, t0 = blockIdx.x * 256;

    const int lr = tid >> 3, lc = (tid & 7) * 4;
    float4 ra[4], rk[8];

    auto ldg = [&](int it) {
        int b = it >> 3, kc = it & 7;
        const float* qa = Q  + ((long)b * Ssz + s0) * 256;
        const float* kb = Ko + ((long)b * Ssz + t0) * 256;
        #pragma unroll
        for (int p = 0; p < 4; p++)
            ra[p] = *(const float4*)&qa[(long)(lr + p * 32) * 256 + kc * 32 + lc];
        #pragma unroll
        for (int p = 0; p < 8; p++)
            rk[p] = *(const float4*)&kb[(long)(lr + p * 32) * 256 + kc * 32 + lc];
    };
    auto sts = [&](int stg) {
        float* Qs = sm + stg * S_STG;
        float* Ks = Qs + 4608;
        #pragma unroll
        for (int p = 0; p < 4; p++)
            *(float4*)&Qs[(lr + p * 32) * 36 + lc] = ra[p];
        #pragma unroll
        for (int p = 0; p < 8; p++)
            *(float4*)&Ks[(lr + p * 32) * 36 + lc] = rk[p];
    };

    float acc[4][8][4];

    ldg(0); sts(0); __syncthreads();

    for (int it = 0; it < 64; it++) {
        const int stg = it & 1;
        if (it + 1 < 64) ldg(it + 1);

        if ((it & 7) == 0) {
            #pragma unroll
            for (int i = 0; i < 4; i++)
                #pragma unroll
                for (int j = 0; j < 8; j++)
                    #pragma unroll
                    for (int r = 0; r < 4; r++) acc[i][j][r] = 0.f;
        }

        const float* Qs = sm + stg * S_STG;
        const float* Ks = Qs + 4608;
        #pragma unroll
        for (int ks = 0; ks < 4; ks++) {
            const int k0 = ks * 8;
            unsigned af[4][4], bf[8][2];
            #pragma unroll
            for (int mi = 0; mi < 4; mi++) {
                int rm = wm + mi * 16;
                af[mi][0] = __float_as_uint(Qs[(rm + grp    ) * 36 + k0 + tg    ]);
                af[mi][1] = __float_as_uint(Qs[(rm + grp + 8) * 36 + k0 + tg    ]);
                af[mi][2] = __float_as_uint(Qs[(rm + grp    ) * 36 + k0 + tg + 4]);
                af[mi][3] = __float_as_uint(Qs[(rm + grp + 8) * 36 + k0 + tg + 4]);
            }
            #pragma unroll
            for (int ni = 0; ni < 8; ni++) {
                int cn = wn + ni * 8 + grp;
                bf[ni][0] = __float_as_uint(Ks[cn * 36 + k0 + tg    ]);
                bf[ni][1] = __float_as_uint(Ks[cn * 36 + k0 + tg + 4]);
            }
            #pragma unroll
            for (int mi = 0; mi < 4; mi++)
                #pragma unroll
                for (int ni = 0; ni < 8; ni++)
                    mma_tf32(acc[mi][ni], af[mi], bf[ni]);
        }

        if ((it & 7) == 7) {
            const int b = it >> 3;
            float* Eb = E + (long)b * SSl;
            #pragma unroll
            for (int mi = 0; mi < 4; mi++) {
                #pragma unroll
                for (int ni = 0; ni < 8; ni++) {
                    int r0 = s0 + wm + mi * 16 + grp;
                    int c0 = t0 + wn + ni * 8 + tg * 2;
                    float e0 = __expf(acc[mi][ni][0] * 0.0625f);
                    float e1 = __expf(acc[mi][ni][1] * 0.0625f);
                    float e2 = __expf(acc[mi][ni][2] * 0.0625f);
                    float e3 = __expf(acc[mi][ni][3] * 0.0625f);
                    *(float2*)&Eb[(long)r0 * Ssz + c0] = make_float2(e0, e1);
                    *(float2*)&Eb[(long)(r0 + 8) * Ssz + c0] = make_float2(e2, e3);
                }
            }
        }
        if (it + 1 < 64) { sts(stg ^ 1); __syncthreads(); }
    }
}

// ---- normalize: E[b,s,t] *= 1/sum_b E[b,s,t], tf32-rounded in place --------
__global__ __launch_bounds__(256, 4) void normalize_kernel(float* __restrict__ E)
{
    long i = ((long)blockIdx.x * 256 + threadIdx.x) * 4;
    float4 e[Bbat];
    float4 s = make_float4(0.f, 0.f, 0.f, 0.f);
    #pragma unroll
    for (int b = 0; b < Bbat; b++) {
        e[b] = *(const float4*)&E[b * SSl + i];
        s.x += e[b].x; s.y += e[b].y; s.z += e[b].z; s.w += e[b].w;
    }
    float4 inv = make_float4(1.f / s.x, 1.f / s.y, 1.f / s.z, 1.f / s.w);
    #pragma unroll
    for (int b = 0; b < Bbat; b++) {
        *(float4*)&E[b * SSl + i] =
            make_float4(tf32r(e[b].x * inv.x), tf32r(e[b].y * inv.y),
                        tf32r(e[b].z * inv.z), tf32r(e[b].w * inv.w));
    }
}

// ---- launch ----------------------------------------------------------------
extern "C" void kernel_launch(void* const* d_in, const int* in_sizes, int n_in,
                              void* d_out, int out_size) {
    const float* x_l = (const float*)d_in[0];
    const float* x_r = (const float*)d_in[1];
    const float* Wq  = (const float*)d_in[2];
    const float* Wk  = (const float*)d_in[3];
    const float* Wv  = (const float*)d_in[4];
    const float* Wo  = (const float*)d_in[5];
    const float* g1  = (const float*)d_in[6];
    const float* b1  = (const float*)d_in[7];
    const float* g2  = (const float*)d_in[8];
    const float* b2  = (const float*)d_in[9];
    float* out = (float*)d_out;

    float *xln, *q, *k, *v, *E, *O, *Wt;
    cudaGetSymbolAddress((void**)&xln, g_xln);
    cudaGetSymbolAddress((void**)&q,   g_q);
    cudaGetSymbolAddress((void**)&k,   g_k);
    cudaGetSymbolAddress((void**)&v,   g_v);
    cudaGetSymbolAddress((void**)&E,   g_E);
    cudaGetSymbolAddress((void**)&O,   g_O);
    cudaGetSymbolAddress((void**)&Wt,  g_Wt);

    cudaFuncSetAttribute(gemm_tc<0>, cudaFuncAttributeMaxDynamicSharedMemorySize, SMEM_G);
    cudaFuncSetAttribute(gemm_tc<2>, cudaFuncAttributeMaxDynamicSharedMemorySize, SMEM_G);
    cudaFuncSetAttribute(tc_scores,  cudaFuncAttributeMaxDynamicSharedMemorySize, SMEM_S);

    wconv_kernel<<<256, 256>>>(Wq, Wk, Wv, Wo, Wt);
    ln_kernel<<<dim3(Ssz / 32, Bbat, 2), 256>>>(x_l, x_r, g1, b1, g2, b2,
                                                xln, xln + BSC);

    for (int s = 0; s < 2; s++) {
        gemm_tc<0><<<dim3(144, 1), 256, SMEM_G>>>(xln + s * BSC, 256, 0,
                                                  Wt + 0 * 65536, 256, 0,
                                                  q + s * BSC, 0, 256, nullptr);
        gemm_tc<0><<<dim3(144, 1), 256, SMEM_G>>>(xln + s * BSC, 256, 0,
                                                  Wt + 1 * 65536, 256, 0,
                                                  k + s * BSC, 0, 256, nullptr);
        gemm_tc<0><<<dim3(144, 1), 256, SMEM_G>>>(xln + s * BSC, 256, 0,
                                                  Wt + 2 * 65536, 256, 0,
                                                  v + s * BSC, 0, 256, nullptr);
    }

    for (int s = 0; s < 2; s++) {
        tc_scores<<<dim3(9, 18), 256, SMEM_S>>>(q + s * BSC, k + (1 - s) * BSC, E);
        normalize_kernel<<<(int)(SSl / 1024), 256>>>(E);
        gemm_tc<0><<<dim3(18, 8), 256, SMEM_G>>>(E, Ssz, SSl,
                                                 v + s * BSC, 256, (long)Ssz * 256,
                                                 O, (long)Ssz * 256, Ssz, nullptr);
        gemm_tc<2><<<dim3(144, 1), 256, SMEM_G>>>(O, 256, 0,
                                                  Wt + 3 * 65536, 256, 0,
                                                  out + s * BSC, 0, 256,
                                                  s ? x_r : x_l);
    }
}